// round 6
// baseline (speedup 1.0000x reference)
#include <cuda_runtime.h>

#define T_STEPS 96
#define BATCH   128

// Output section offsets (floats), tuple order:
// mu_filt, sigma_filt, mu_pred, sigma_pred, latent_means, latent_variances, S
#define OFF_MUF   0
#define OFF_SIGF  393216
#define OFF_MUP   12976128
#define OFF_SIGP  13369344
#define OFF_LM    25952256
#define OFF_LV    26738688
#define OFF_S     51904512

#define PZ 36   // 32-wide rows padded: 144B, 16B-aligned
#define PA 20   // 16-wide rows padded: 80B, 16B-aligned

__device__ __forceinline__ float dot4(float4 a, float4 b) {
    return a.x * b.x + a.y * b.y + a.z * b.z + a.w * b.w;
}

__global__ __launch_bounds__(256, 1)
void kalman_kernel(const float* __restrict__ obs,
                   const float* __restrict__ Ag_all,
                   const float* __restrict__ Cg_all,
                   const float* __restrict__ Dg_all,
                   float* __restrict__ out)
{
    const int tid  = threadIdx.x;

    // ---------------- writer blocks: latent_variances (input-independent) ----
    if (blockIdx.x >= BATCH) {
        float* out_lv = out + OFF_LV;
        int wb = blockIdx.x - BATCH;          // 0..19
        for (int t = 0; t < T_STEPS; ++t) {
            float d0 = (t >= 2) ? 0.08f : 0.f;
            float d1 = (t <  4) ? 20.f  : 0.f;
            float4* dst = (float4*)(out_lv + (size_t)t * BATCH * 2048);
            for (int e4 = wb * 256 + tid; e4 < 65536; e4 += 20 * 256) {
                int v2 = (e4 * 4) & 2047;
                int l  = v2 >> 10;
                int ij = v2 & 1023;
                int i  = ij >> 5, j0 = ij & 31;
                float dv = l ? d1 : d0;
                bool hit = ((i >> 2) == (j0 >> 2));
                float4 v;
                v.x = (hit && (i & 3) == 0) ? dv : 0.f;
                v.y = (hit && (i & 3) == 1) ? dv : 0.f;
                v.z = (hit && (i & 3) == 2) ? dv : 0.f;
                v.w = (hit && (i & 3) == 3) ? dv : 0.f;
                dst[e4] = v;
            }
        }
        return;
    }

    const int b    = blockIdx.x;
    const int lane = tid & 31;
    const int wid  = tid >> 5;       // 0..7

    __shared__ __align__(16) float sigB[2][32][PZ]; // sigma ping-pong (symmetric)
    __shared__ __align__(16) float Ush [32][PZ];    // U = A @ sigma
    __shared__ __align__(16) float Rsh [32][PZ];    // 20*D@D^T (t<4)
    __shared__ __align__(16) float Am  [32][PZ];    // A[b,t+1,0]
    __shared__ __align__(16) float Dm  [32][PZ];    // D[b,t+1,0]
    __shared__ __align__(16) float Ct  [16][PZ];    // C[b,t]
    __shared__ __align__(16) float CSr [16][PZ];    // CS = C@sigma, row-major
    __shared__ __align__(16) float CSc [32][PA];    // W = sigma C^T (rows = z)
    __shared__ __align__(16) float Vsh [32][PA];    // V = A @ W
    __shared__ __align__(16) float Gsh [32][PA];    // G = V @ Sinv
    __shared__ __align__(16) float Ksh [32][PA];    // K = W @ Sinv
    __shared__ __align__(16) float Sinv[16][PA];
    __shared__ __align__(16) float Ssh [16][PA];
    __shared__ __align__(16) float muB[2][32];
    __shared__ __align__(16) float amv[32], dchv[32], rv[16], ov[16];
    __shared__ __align__(16) float chain[24][32];

    float* out_muf  = out + OFF_MUF;
    float* out_sigf = out + OFF_SIGF;
    float* out_mup  = out + OFF_MUP;
    float* out_sigp = out + OFF_SIGP;
    float* out_lm   = out + OFF_LM;
    float* out_S    = out + OFF_S;

    // ---------------- Prologue: top-level latent chain ----------------
    if (tid < 32) chain[0][tid] = 0.01f;
    {
        float4 pf[3];
        #pragma unroll
        for (int s = 0; s < 3; ++s) {
            const float* Ag = Ag_all + ((size_t)(b * T_STEPS + 4 * (s + 1)) * 3 + 2) * 1024;
            pf[s] = *(const float4*)(Ag + tid * 4);
        }
        __syncthreads();
        for (int j = 1; j <= 23; ++j) {
            int s = (j - 1) % 3;
            *(float4*)&Am[tid >> 3][(tid & 7) * 4] = pf[s];
            if (j + 3 <= 23) {
                const float* Ag = Ag_all + ((size_t)(b * T_STEPS + 4 * (j + 3)) * 3 + 2) * 1024;
                pf[s] = *(const float4*)(Ag + tid * 4);
            }
            __syncthreads();
            if (tid < 32) {
                const float4* ar = (const float4*)&Am[tid][0];
                const float4* ch = (const float4*)&chain[j - 1][0];
                float sm = 0.f;
                #pragma unroll
                for (int q = 0; q < 8; ++q) sm += dot4(ar[q], ch[q]);
                chain[j][tid] = sm;
            }
            __syncthreads();
        }
    }

    // ---------------- init state + t=0 prior outputs + step-0/1 operands ----
    float4 rA, rD, rC = make_float4(0, 0, 0, 0);
    float  rO = 0.f;
    {
        if (tid < 128)
            *(float4*)&Ct[tid >> 3][(tid & 7) * 4] =
                *(const float4*)(Cg_all + (size_t)(b * T_STEPS) * 512 + tid * 4);
        if (tid < 16) ov[tid] = obs[(size_t)b * 16 + tid];
        {
            int row = tid >> 3, c0 = (tid & 7) * 4;
            float4 sv = make_float4(0, 0, 0, 0);
            if (row >= c0 && row < c0 + 4) {
                int d = row - c0;
                sv.x = (d == 0) ? 20.f : 0.f;
                sv.y = (d == 1) ? 20.f : 0.f;
                sv.z = (d == 2) ? 20.f : 0.f;
                sv.w = (d == 3) ? 20.f : 0.f;
            }
            *(float4*)&sigB[0][row][c0] = sv;
            *(float4*)(out_sigp + (size_t)b * 1024 + tid * 4) = sv;
        }
        if (tid < 32) muB[0][tid] = 0.f;
        if (tid < 8)
            *(float4*)(out_mup + (size_t)b * 32 + tid * 4) = make_float4(0, 0, 0, 0);
        rA = *(const float4*)(Ag_all + (size_t)(b * T_STEPS + 1) * 3 * 1024 + tid * 4);
        rD = *(const float4*)(Dg_all + (size_t)(b * T_STEPS + 1) * 2 * 1024 + tid * 4);
    }
    __syncthreads();

    // ---------------- main sequential filter ----------------
    for (int t = 0; t < T_STEPS; ++t) {
        const size_t tb = (size_t)t * BATCH + b;
        float (*sgc)[PZ] = sigB[t & 1];
        float (*sgn)[PZ] = sigB[(t + 1) & 1];
        float* muc = muB[t & 1];
        float* mun = muB[(t + 1) & 1];

        float4 scol[8];   // register-cached sigma column `lane` (reused in P2)
        float4 al[8];     // A row `lane` (loaded P3/P4)
        float  t1[4];     // (U A^T)[wid+8ii][lane] (computed P3/P4, used P5)

        // ---- P1: STS A/D[t+1]; prefetch; CS = C@sigma; r = o - C@mu ----
        {
            int ar2 = tid >> 3, ac = (tid & 7) * 4;
            *(float4*)&Am[ar2][ac] = rA;
            *(float4*)&Dm[ar2][ac] = rD;
            if (t + 2 < T_STEPS) {
                rA = *(const float4*)(Ag_all + (size_t)(b * T_STEPS + t + 2) * 3 * 1024 + tid * 4);
                rD = *(const float4*)(Dg_all + (size_t)(b * T_STEPS + t + 2) * 2 * 1024 + tid * 4);
            }
            if (t + 1 < T_STEPS) {
                if (tid >= 32 && tid < 160)
                    rC = *(const float4*)(Cg_all + (size_t)(b * T_STEPS + t + 1) * 512 + (tid - 32) * 4);
                if (tid >= 32 && tid < 48)
                    rO = obs[(size_t)((t + 1) * BATCH + b) * 16 + (tid - 32)];
            }
            const float4* sc = (const float4*)&sgc[lane][0];
            const float4* c0 = (const float4*)&Ct[wid][0];
            const float4* c1 = (const float4*)&Ct[wid + 8][0];
            float s0 = 0.f, s1 = 0.f;
            #pragma unroll
            for (int q = 0; q < 8; ++q) {
                float4 g = sc[q];
                scol[q] = g;
                s0 += dot4(c0[q], g);
                s1 += dot4(c1[q], g);
            }
            CSr[wid][lane] = s0;      CSr[wid + 8][lane] = s1;
            CSc[lane][wid] = s0;      CSc[lane][wid + 8] = s1;
            if (tid < 16) {
                const float4* c4 = (const float4*)&Ct[tid][0];
                const float4* m4 = (const float4*)muc;
                float rr = ov[tid];
                #pragma unroll
                for (int q = 0; q < 8; ++q) rr -= dot4(c4[q], m4[q]);
                rv[tid] = rr;
            }
        }
        __syncthreads();

        // ---- P2: S = CS@C^T + 0.03 I (+ STG); U = A@sigma; V = A@W ----
        {
            int i = tid >> 4, j = tid & 15;
            const float4* a4 = (const float4*)&CSr[i][0];
            const float4* c4 = (const float4*)&Ct[j][0];
            float s = (i == j) ? 0.03f : 0.f;
            #pragma unroll
            for (int q = 0; q < 8; ++q) s += dot4(a4[q], c4[q]);
            Ssh[i][j] = s;
            out_S[tb * 256 + tid] = s;

            if (t + 1 < T_STEPS) {
                float4 wrr[8];
                #pragma unroll
                for (int q = 0; q < 8; ++q)
                    wrr[q] = ((const float4*)&CSr[lane & 15][0])[q];
                #pragma unroll
                for (int ii = 0; ii < 4; ++ii) {
                    int r = wid + 8 * ii;
                    const float4* ar = (const float4*)&Am[r][0];
                    float u = 0.f, v = 0.f;
                    #pragma unroll
                    for (int q = 0; q < 8; ++q) {
                        float4 a = ar[q];
                        u += dot4(a, scol[q]);
                        v += dot4(a, wrr[q]);
                    }
                    Ush[r][lane] = u;
                    Vsh[r][lane & 15] = v;
                }
            }
        }
        __syncthreads();

        // ---- P3: warp0 GJ inverse; warps 1-7: t1 = U A^T, Ct/ov STS, extras ----
        if (wid == 0) {
            const int lrow = lane & 15;
            float M[16];
            const float4* sr = (const float4*)&Ssh[lrow][0];
            #pragma unroll
            for (int q = 0; q < 4; ++q) {
                float4 v = sr[q];
                M[4 * q + 0] = v.x; M[4 * q + 1] = v.y;
                M[4 * q + 2] = v.z; M[4 * q + 3] = v.w;
            }
            #pragma unroll
            for (int j = 0; j < 16; ++j) {
                float pj = __shfl_sync(0xffffffffu, M[j], j);
                float ip;
                asm("rcp.approx.ftz.f32 %0, %1;" : "=f"(ip) : "f"(pj));
                float f  = M[j];
                bool isj = (lrow == j);
                #pragma unroll
                for (int kk = 1; kk < 16; ++kk) {
                    int k = (j + kk) & 15;     // k = j+1 first: shortens pivot chain
                    float rj = __shfl_sync(0xffffffffu, M[k], j);
                    float v  = rj * ip;
                    M[k] = isj ? v : fmaf(-f, v, M[k]);
                }
                M[j] = isj ? ip : (-f * ip);
            }
            if (lane < 16) {
                float4* dst = (float4*)&Sinv[lane][0];
                #pragma unroll
                for (int q = 0; q < 4; ++q)
                    dst[q] = make_float4(M[4 * q], M[4 * q + 1], M[4 * q + 2], M[4 * q + 3]);
            }
        } else {
            int wtid = tid - 32;    // 0..223
            if (wtid < 16) {
                float4 v = make_float4(0, 0, 0, 0);
                if (wtid >= 8) v = *(const float4*)&chain[t >> 2][(wtid - 8) * 4];
                *(float4*)(out_lm + tb * 64 + wtid * 4) = v;
            }
            if (t + 1 < T_STEPS) {
                if (tid < 160) {
                    int q2 = tid - 32;
                    *(float4*)&Ct[q2 >> 3][(q2 & 7) * 4] = rC;
                }
                if (tid < 48) ov[tid - 32] = rO;
                // t1 = (U A^T) rows wid+8ii at column lane (hidden under GJ)
                #pragma unroll
                for (int q = 0; q < 8; ++q)
                    al[q] = ((const float4*)&Am[lane][0])[q];
                #pragma unroll
                for (int ii = 0; ii < 4; ++ii) {
                    const float4* ur = (const float4*)&Ush[wid + 8 * ii][0];
                    float s = 0.f;
                    #pragma unroll
                    for (int q = 0; q < 8; ++q) s += dot4(ur[q], al[q]);
                    t1[ii] = s;
                }
                if (wid == 7) {   // Amu + Dch
                    const float4* al7 = (const float4*)&Am[lane][0];
                    const float4* dl7 = (const float4*)&Dm[lane][0];
                    const float4* m4  = (const float4*)muc;
                    const float4* ch  = (const float4*)&chain[t >> 2][0];
                    float am = 0.f, dc = 0.f;
                    #pragma unroll
                    for (int q = 0; q < 8; ++q) {
                        am += dot4(al7[q], m4[q]);
                        dc += dot4(dl7[q], ch[q]);
                    }
                    amv[lane]  = am;
                    dchv[lane] = dc;
                }
                if (t < 4) {     // R20 = 20 * D @ D^T
                    int ww = wid - 1;
                    float4 dcol[8];
                    #pragma unroll
                    for (int q = 0; q < 8; ++q) dcol[q] = ((const float4*)&Dm[lane][0])[q];
                    #pragma unroll
                    for (int m = 0; m < 5; ++m) {
                        int r = ww + 7 * m;
                        if (r < 32) {
                            const float4* dr = (const float4*)&Dm[r][0];
                            float s = 0.f;
                            #pragma unroll
                            for (int q = 0; q < 8; ++q) s += dot4(dr[q], dcol[q]);
                            Rsh[r][lane] = 20.f * s;
                        }
                    }
                }
            }
        }
        __syncthreads();

        // ---- P4: K = W@Sinv, G = V@Sinv; warp0 computes its al/t1 ----
        {
            const float4* i0 = (const float4*)&Sinv[wid][0];
            const float4* i1 = (const float4*)&Sinv[wid + 8][0];
            {
                const float4* cz = (const float4*)&CSc[lane][0];
                float s0 = 0.f, s1 = 0.f;
                #pragma unroll
                for (int q = 0; q < 4; ++q) {
                    float4 x = cz[q];
                    s0 += dot4(x, i0[q]);
                    s1 += dot4(x, i1[q]);
                }
                Ksh[lane][wid]     = s0;
                Ksh[lane][wid + 8] = s1;
            }
            if (t + 1 < T_STEPS) {
                const float4* vz = (const float4*)&Vsh[lane][0];
                float g0 = 0.f, g1 = 0.f;
                #pragma unroll
                for (int q = 0; q < 4; ++q) {
                    float4 x = vz[q];
                    g0 += dot4(x, i0[q]);
                    g1 += dot4(x, i1[q]);
                }
                Gsh[lane][wid]     = g0;
                Gsh[lane][wid + 8] = g1;
                if (wid == 0) {
                    #pragma unroll
                    for (int q = 0; q < 8; ++q)
                        al[q] = ((const float4*)&Am[lane][0])[q];
                    #pragma unroll
                    for (int ii = 0; ii < 4; ++ii) {
                        const float4* ur = (const float4*)&Ush[8 * ii][0];
                        float s = 0.f;
                        #pragma unroll
                        for (int q = 0; q < 8; ++q) s += dot4(ur[q], al[q]);
                        t1[ii] = s;
                    }
                }
            }
        }
        __syncthreads();

        // ---- P5: sigz -> sigf; sigma' = t1 - G V^T + Q (+R20); mu' ----
        {
            float4 wl[4];
            #pragma unroll
            for (int q = 0; q < 4; ++q) wl[q] = ((const float4*)&CSc[lane][0])[q];
            #pragma unroll
            for (int ii = 0; ii < 4; ++ii) {
                int i = wid + 8 * ii;
                const float4* kr = (const float4*)&Ksh[i][0];
                float z = sgc[i][lane];
                #pragma unroll
                for (int q = 0; q < 4; ++q) z -= dot4(kr[q], wl[q]);
                out_sigf[tb * 1024 + i * 32 + lane] = z;
            }
            if (tid < 32) {   // mu_filt
                const float4* kk = (const float4*)&Ksh[tid][0];
                const float4* r4 = (const float4*)rv;
                float m = muc[tid];
                #pragma unroll
                for (int q = 0; q < 4; ++q) m += dot4(kk[q], r4[q]);
                out_muf[tb * 32 + tid] = m;
            }
            if (t + 1 < T_STEPS) {
                const size_t tb2 = tb + BATCH;   // (t+1)*BATCH + b
                float4 vl[4];
                #pragma unroll
                for (int q = 0; q < 4; ++q) vl[q] = ((const float4*)&Vsh[lane][0])[q];
                #pragma unroll
                for (int ii = 0; ii < 4; ++ii) {
                    int i = wid + 8 * ii;
                    const float4* gr = (const float4*)&Gsh[i][0];
                    float s = t1[ii];
                    #pragma unroll
                    for (int q = 0; q < 4; ++q) s -= dot4(gr[q], vl[q]);
                    if (i == lane) s += 0.08f;
                    if (t < 4)     s += Rsh[i][lane];
                    sgn[i][lane] = s;
                    out_sigp[tb2 * 1024 + i * 32 + lane] = s;
                }
                if (tid >= 32 && tid < 64) {   // mu' = Amu + G r + Dch
                    int l = lane;
                    const float4* gr = (const float4*)&Gsh[l][0];
                    const float4* r4 = (const float4*)rv;
                    float m = amv[l] + dchv[l];
                    #pragma unroll
                    for (int q = 0; q < 4; ++q) m += dot4(gr[q], r4[q]);
                    mun[l] = m;
                    out_mup[tb2 * 32 + l] = m;
                }
            }
        }
        __syncthreads();
    }
}

extern "C" void kernel_launch(void* const* d_in, const int* in_sizes, int n_in,
                              void* d_out, int out_size) {
    const float* obs = (const float*)d_in[0];
    const float* A   = (const float*)d_in[1];
    const float* C   = (const float*)d_in[2];
    const float* D   = (const float*)d_in[3];
    kalman_kernel<<<BATCH + 20, 256>>>(obs, A, C, D, (float*)d_out);
}

// round 7
// speedup vs baseline: 1.1396x; 1.1396x over previous
#include <cuda_runtime.h>

#define T_STEPS 96
#define BATCH   128

// Output section offsets (floats), tuple order:
// mu_filt, sigma_filt, mu_pred, sigma_pred, latent_means, latent_variances, S
#define OFF_MUF   0
#define OFF_SIGF  393216
#define OFF_MUP   12976128
#define OFF_SIGP  13369344
#define OFF_LM    25952256
#define OFF_LV    26738688
#define OFF_S     51904512

#define PZ 36   // 32-wide rows padded: 144B, 16B-aligned
#define PA 20   // 16-wide rows padded: 80B, 16B-aligned

__device__ __forceinline__ float dot4(float4 a, float4 b) {
    return a.x * b.x + a.y * b.y + a.z * b.z + a.w * b.w;
}

__global__ __launch_bounds__(256, 1)
void kalman_kernel(const float* __restrict__ obs,
                   const float* __restrict__ Ag_all,
                   const float* __restrict__ Cg_all,
                   const float* __restrict__ Dg_all,
                   float* __restrict__ out)
{
    const int tid  = threadIdx.x;

    // ---------------- writer blocks: latent_variances (input-independent) ----
    if (blockIdx.x >= BATCH) {
        float* out_lv = out + OFF_LV;
        int wb = blockIdx.x - BATCH;          // 0..19
        for (int t = 0; t < T_STEPS; ++t) {
            float d0 = (t >= 2) ? 0.08f : 0.f;
            float d1 = (t <  4) ? 20.f  : 0.f;
            float4* dst = (float4*)(out_lv + (size_t)t * BATCH * 2048);
            for (int e4 = wb * 256 + tid; e4 < 65536; e4 += 20 * 256) {
                int v2 = (e4 * 4) & 2047;
                int l  = v2 >> 10;
                int ij = v2 & 1023;
                int i  = ij >> 5, j0 = ij & 31;
                float dv = l ? d1 : d0;
                bool hit = ((i >> 2) == (j0 >> 2));
                float4 v;
                v.x = (hit && (i & 3) == 0) ? dv : 0.f;
                v.y = (hit && (i & 3) == 1) ? dv : 0.f;
                v.z = (hit && (i & 3) == 2) ? dv : 0.f;
                v.w = (hit && (i & 3) == 3) ? dv : 0.f;
                dst[e4] = v;
            }
        }
        return;
    }

    const int b    = blockIdx.x;
    const int lane = tid & 31;
    const int wid  = tid >> 5;       // 0..7

    __shared__ __align__(16) float sigB[2][32][PZ]; // sigma ping-pong (symmetric)
    __shared__ __align__(16) float Ush [32][PZ];    // U = A @ sigma
    __shared__ __align__(16) float Rsh [32][PZ];    // 20*D@D^T (t<4)
    __shared__ __align__(16) float Am  [32][PZ];    // A[b,t+1,0]
    __shared__ __align__(16) float Dm  [32][PZ];    // D[b,t+1,0]
    __shared__ __align__(16) float Ct  [16][PZ];    // C[b,t]
    __shared__ __align__(16) float CSr [16][PZ];    // CS = C@sigma, row-major
    __shared__ __align__(16) float CSc [32][PA];    // W = sigma C^T (rows = z)
    __shared__ __align__(16) float Vsh [32][PA];    // V = A @ W
    __shared__ __align__(16) float Gsh [32][PA];    // G = V @ Sinv
    __shared__ __align__(16) float Ksh [32][PA];    // K = W @ Sinv
    __shared__ __align__(16) float Sinv[16][PA];
    __shared__ __align__(16) float Ssh [16][PA];
    __shared__ __align__(16) float muB[2][32];
    __shared__ __align__(16) float amv[32], dchv[32], rv[16], ov[16];
    __shared__ __align__(16) float chain[24][32];

    float* out_muf  = out + OFF_MUF;
    float* out_sigf = out + OFF_SIGF;
    float* out_mup  = out + OFF_MUP;
    float* out_sigp = out + OFF_SIGP;
    float* out_lm   = out + OFF_LM;
    float* out_S    = out + OFF_S;

    // ---------------- Prologue: top-level latent chain ----------------
    if (tid < 32) chain[0][tid] = 0.01f;
    {
        float4 pf[3];
        #pragma unroll
        for (int s = 0; s < 3; ++s) {
            const float* Ag = Ag_all + ((size_t)(b * T_STEPS + 4 * (s + 1)) * 3 + 2) * 1024;
            pf[s] = *(const float4*)(Ag + tid * 4);
        }
        __syncthreads();
        for (int j = 1; j <= 23; ++j) {
            int s = (j - 1) % 3;
            *(float4*)&Am[tid >> 3][(tid & 7) * 4] = pf[s];
            if (j + 3 <= 23) {
                const float* Ag = Ag_all + ((size_t)(b * T_STEPS + 4 * (j + 3)) * 3 + 2) * 1024;
                pf[s] = *(const float4*)(Ag + tid * 4);
            }
            __syncthreads();
            if (tid < 32) {
                const float4* ar = (const float4*)&Am[tid][0];
                const float4* ch = (const float4*)&chain[j - 1][0];
                float sm = 0.f;
                #pragma unroll
                for (int q = 0; q < 8; ++q) sm += dot4(ar[q], ch[q]);
                chain[j][tid] = sm;
            }
            __syncthreads();
        }
    }

    // ---------------- init state + t=0 prior outputs + step-0/1 operands ----
    float4 rA, rD, rC = make_float4(0, 0, 0, 0);
    float  rO = 0.f;
    {
        if (tid < 128)
            *(float4*)&Ct[tid >> 3][(tid & 7) * 4] =
                *(const float4*)(Cg_all + (size_t)(b * T_STEPS) * 512 + tid * 4);
        if (tid < 16) ov[tid] = obs[(size_t)b * 16 + tid];
        {
            int row = tid >> 3, c0 = (tid & 7) * 4;
            float4 sv = make_float4(0, 0, 0, 0);
            if (row >= c0 && row < c0 + 4) {
                int d = row - c0;
                sv.x = (d == 0) ? 20.f : 0.f;
                sv.y = (d == 1) ? 20.f : 0.f;
                sv.z = (d == 2) ? 20.f : 0.f;
                sv.w = (d == 3) ? 20.f : 0.f;
            }
            *(float4*)&sigB[0][row][c0] = sv;
            *(float4*)(out_sigp + (size_t)b * 1024 + tid * 4) = sv;
        }
        if (tid < 32) muB[0][tid] = 0.f;
        if (tid < 8)
            *(float4*)(out_mup + (size_t)b * 32 + tid * 4) = make_float4(0, 0, 0, 0);
        rA = *(const float4*)(Ag_all + (size_t)(b * T_STEPS + 1) * 3 * 1024 + tid * 4);
        rD = *(const float4*)(Dg_all + (size_t)(b * T_STEPS + 1) * 2 * 1024 + tid * 4);
    }
    __syncthreads();

    // ---------------- main sequential filter ----------------
    for (int t = 0; t < T_STEPS; ++t) {
        const size_t tb = (size_t)t * BATCH + b;
        float (*sgc)[PZ] = sigB[t & 1];
        float (*sgn)[PZ] = sigB[(t + 1) & 1];
        float* muc = muB[t & 1];
        float* mun = muB[(t + 1) & 1];

        float4 scol[8];   // register-cached sigma column `lane` (reused in P3)

        // ---- P1: STS A/D[t+1]; prefetch; CS = C@sigma; r = o - C@mu ----
        {
            int ar2 = tid >> 3, ac = (tid & 7) * 4;
            *(float4*)&Am[ar2][ac] = rA;
            *(float4*)&Dm[ar2][ac] = rD;
            if (t + 2 < T_STEPS) {
                rA = *(const float4*)(Ag_all + (size_t)(b * T_STEPS + t + 2) * 3 * 1024 + tid * 4);
                rD = *(const float4*)(Dg_all + (size_t)(b * T_STEPS + t + 2) * 2 * 1024 + tid * 4);
            }
            if (t + 1 < T_STEPS) {
                if (tid < 128)
                    rC = *(const float4*)(Cg_all + (size_t)(b * T_STEPS + t + 1) * 512 + tid * 4);
                if (tid < 16)
                    rO = obs[(size_t)((t + 1) * BATCH + b) * 16 + tid];
            }
            const float4* sc = (const float4*)&sgc[lane][0];
            const float4* c0 = (const float4*)&Ct[wid][0];
            const float4* c1 = (const float4*)&Ct[wid + 8][0];
            float s0 = 0.f, s1 = 0.f;
            #pragma unroll
            for (int q = 0; q < 8; ++q) {
                float4 g = sc[q];
                scol[q] = g;
                s0 += dot4(c0[q], g);
                s1 += dot4(c1[q], g);
            }
            CSr[wid][lane] = s0;      CSr[wid + 8][lane] = s1;
            CSc[lane][wid] = s0;      CSc[lane][wid + 8] = s1;
            if (tid < 16) {
                const float4* c4 = (const float4*)&Ct[tid][0];
                const float4* m4 = (const float4*)muc;
                float rr = ov[tid];
                #pragma unroll
                for (int q = 0; q < 8; ++q) rr -= dot4(c4[q], m4[q]);
                rv[tid] = rr;
            }
        }
        __syncthreads();

        // ---- P2: S = CS@C^T + 0.03 I; write S out ----
        {
            int i = tid >> 4, j = tid & 15;
            const float4* a4 = (const float4*)&CSr[i][0];
            const float4* c4 = (const float4*)&Ct[j][0];
            float s = (i == j) ? 0.03f : 0.f;
            #pragma unroll
            for (int q = 0; q < 8; ++q) s += dot4(a4[q], c4[q]);
            Ssh[i][j] = s;
            out_S[tb * 256 + tid] = s;
        }
        __syncthreads();

        // ---- P3: warp0 GJ inverse; warps 1-7: U, V, Amu, Dch, R20, lm ----
        if (wid == 0) {
            const int lrow = lane & 15;
            float M[16];
            const float4* sr = (const float4*)&Ssh[lrow][0];
            #pragma unroll
            for (int q = 0; q < 4; ++q) {
                float4 v = sr[q];
                M[4 * q + 0] = v.x; M[4 * q + 1] = v.y;
                M[4 * q + 2] = v.z; M[4 * q + 3] = v.w;
            }
            #pragma unroll
            for (int j = 0; j < 16; ++j) {
                float pj = __shfl_sync(0xffffffffu, M[j], j);
                float ip;
                asm("rcp.approx.ftz.f32 %0, %1;" : "=f"(ip) : "f"(pj));
                float f  = M[j];
                bool isj = (lrow == j);
                #pragma unroll
                for (int kk = 1; kk < 16; ++kk) {
                    int k = (j + kk) & 15;     // k = j+1 first: shortens pivot chain
                    float rj = __shfl_sync(0xffffffffu, M[k], j);
                    float v  = rj * ip;
                    M[k] = isj ? v : fmaf(-f, v, M[k]);
                }
                M[j] = isj ? ip : (-f * ip);
            }
            if (lane < 16) {
                float4* dst = (float4*)&Sinv[lane][0];
                #pragma unroll
                for (int q = 0; q < 4; ++q)
                    dst[q] = make_float4(M[4 * q], M[4 * q + 1], M[4 * q + 2], M[4 * q + 3]);
            }
        } else {
            int ww   = wid - 1;     // 0..6
            int wtid = tid - 32;    // 0..223
            if (wtid < 16) {
                float4 v = make_float4(0, 0, 0, 0);
                if (wtid >= 8) v = *(const float4*)&chain[t >> 2][(wtid - 8) * 4];
                *(float4*)(out_lm + tb * 64 + wtid * 4) = v;
            }
            if (t + 1 < T_STEPS) {
                // U = A @ sigma (rows ww + 7m), V = A @ W
                float4 wr[8];
                #pragma unroll
                for (int q = 0; q < 8; ++q) wr[q] = ((const float4*)&CSr[lane & 15][0])[q];
                #pragma unroll
                for (int m = 0; m < 5; ++m) {
                    int r = ww + 7 * m;
                    if (r < 32) {
                        const float4* ar = (const float4*)&Am[r][0];
                        float u = 0.f, v = 0.f;
                        #pragma unroll
                        for (int q = 0; q < 8; ++q) {
                            float4 a = ar[q];
                            u += dot4(a, scol[q]);
                            v += dot4(a, wr[q]);
                        }
                        Ush[r][lane] = u;
                        Vsh[r][lane & 15] = v;
                    }
                }
                if (ww == 6) {   // Amu + Dch (warp 7, lightest U load)
                    const float4* al7 = (const float4*)&Am[lane][0];
                    const float4* dl7 = (const float4*)&Dm[lane][0];
                    const float4* m4  = (const float4*)muc;
                    const float4* ch  = (const float4*)&chain[t >> 2][0];
                    float am = 0.f, dc = 0.f;
                    #pragma unroll
                    for (int q = 0; q < 8; ++q) {
                        am += dot4(al7[q], m4[q]);
                        dc += dot4(dl7[q], ch[q]);
                    }
                    amv[lane]  = am;
                    dchv[lane] = dc;
                }
                if (t < 4) {     // R20 = 20 * D @ D^T
                    float4 dcol[8];
                    #pragma unroll
                    for (int q = 0; q < 8; ++q) dcol[q] = ((const float4*)&Dm[lane][0])[q];
                    #pragma unroll
                    for (int m = 0; m < 5; ++m) {
                        int r = ww + 7 * m;
                        if (r < 32) {
                            const float4* dr = (const float4*)&Dm[r][0];
                            float s = 0.f;
                            #pragma unroll
                            for (int q = 0; q < 8; ++q) s += dot4(dr[q], dcol[q]);
                            Rsh[r][lane] = 20.f * s;
                        }
                    }
                }
            }
        }
        __syncthreads();

        // ---- P4: K = W@Sinv, G = V@Sinv (register-carry wl/vl to P5);
        //          al load; t1 rows 0,1; STS next C/obs ----
        float4 al[8];     // A row `lane` (used for t1)
        float4 wl[4];     // CSc[lane] — carried to P5 for sigf
        float4 vl[4];     // Vsh[lane] — carried to P5 for sigma'
        float  t1a = 0.f, t1b = 0.f;   // (U A^T)[wid][lane], [wid+8][lane]
        {
            const float4* i0 = (const float4*)&Sinv[wid][0];
            const float4* i1 = (const float4*)&Sinv[wid + 8][0];
            {
                #pragma unroll
                for (int q = 0; q < 4; ++q) wl[q] = ((const float4*)&CSc[lane][0])[q];
                float s0 = 0.f, s1 = 0.f;
                #pragma unroll
                for (int q = 0; q < 4; ++q) {
                    float4 x = wl[q];
                    s0 += dot4(x, i0[q]);
                    s1 += dot4(x, i1[q]);
                }
                Ksh[lane][wid]     = s0;
                Ksh[lane][wid + 8] = s1;
            }
            if (t + 1 < T_STEPS) {
                #pragma unroll
                for (int q = 0; q < 4; ++q) vl[q] = ((const float4*)&Vsh[lane][0])[q];
                float g0 = 0.f, g1 = 0.f;
                #pragma unroll
                for (int q = 0; q < 4; ++q) {
                    float4 x = vl[q];
                    g0 += dot4(x, i0[q]);
                    g1 += dot4(x, i1[q]);
                }
                Gsh[lane][wid]     = g0;
                Gsh[lane][wid + 8] = g1;
                #pragma unroll
                for (int q = 0; q < 8; ++q) al[q] = ((const float4*)&Am[lane][0])[q];
                // t1 rows 0,1 (Ush stable since P3)
                const float4* u0 = (const float4*)&Ush[wid][0];
                const float4* u1 = (const float4*)&Ush[wid + 8][0];
                #pragma unroll
                for (int q = 0; q < 8; ++q) {
                    t1a += dot4(u0[q], al[q]);
                    t1b += dot4(u1[q], al[q]);
                }
                if (tid < 128) *(float4*)&Ct[tid >> 3][(tid & 7) * 4] = rC;
                if (tid < 16)  ov[tid] = rO;
            }
        }
        __syncthreads();

        // ---- P5: sigz -> sigf; sigma' = t1 - G V^T + Q (+R20); mu' ----
        {
            #pragma unroll
            for (int ii = 0; ii < 4; ++ii) {
                int i = wid + 8 * ii;
                const float4* kr = (const float4*)&Ksh[i][0];
                float z = sgc[i][lane];
                #pragma unroll
                for (int q = 0; q < 4; ++q) z -= dot4(kr[q], wl[q]);
                out_sigf[tb * 1024 + i * 32 + lane] = z;
            }
            if (tid < 32) {   // mu_filt
                const float4* kk = (const float4*)&Ksh[tid][0];
                const float4* r4 = (const float4*)rv;
                float m = muc[tid];
                #pragma unroll
                for (int q = 0; q < 4; ++q) m += dot4(kk[q], r4[q]);
                out_muf[tb * 32 + tid] = m;
            }
            if (t + 1 < T_STEPS) {
                const size_t tb2 = tb + BATCH;   // (t+1)*BATCH + b
                // t1 rows 2,3 computed here; rows 0,1 carried from P4
                float t1c = 0.f, t1d = 0.f;
                {
                    const float4* u2 = (const float4*)&Ush[wid + 16][0];
                    const float4* u3 = (const float4*)&Ush[wid + 24][0];
                    #pragma unroll
                    for (int q = 0; q < 8; ++q) {
                        t1c += dot4(u2[q], al[q]);
                        t1d += dot4(u3[q], al[q]);
                    }
                }
                float t1v[4] = {t1a, t1b, t1c, t1d};
                #pragma unroll
                for (int ii = 0; ii < 4; ++ii) {
                    int i = wid + 8 * ii;
                    const float4* gr = (const float4*)&Gsh[i][0];
                    float s = t1v[ii];
                    #pragma unroll
                    for (int q = 0; q < 4; ++q) s -= dot4(gr[q], vl[q]);
                    if (i == lane) s += 0.08f;
                    if (t < 4)     s += Rsh[i][lane];
                    sgn[i][lane] = s;
                    out_sigp[tb2 * 1024 + i * 32 + lane] = s;
                }
                if (tid >= 32 && tid < 64) {   // mu' = Amu + G r + Dch
                    int l = lane;
                    const float4* gr = (const float4*)&Gsh[l][0];
                    const float4* r4 = (const float4*)rv;
                    float m = amv[l] + dchv[l];
                    #pragma unroll
                    for (int q = 0; q < 4; ++q) m += dot4(gr[q], r4[q]);
                    mun[l] = m;
                    out_mup[tb2 * 32 + l] = m;
                }
            }
        }
        __syncthreads();
    }
}

extern "C" void kernel_launch(void* const* d_in, const int* in_sizes, int n_in,
                              void* d_out, int out_size) {
    const float* obs = (const float*)d_in[0];
    const float* A   = (const float*)d_in[1];
    const float* C   = (const float*)d_in[2];
    const float* D   = (const float*)d_in[3];
    kalman_kernel<<<BATCH + 20, 256>>>(obs, A, C, D, (float*)d_out);
}